// round 5
// baseline (speedup 1.0000x reference)
#include <cuda_runtime.h>
#include <math.h>

#define BGRAPHS 512
#define NP      512
#define DIM     256
#define TOPK    32
#define TOTAL_NODES (BGRAPHS * NP)

// 1 MB scratch for gate values (allocation-free: device global)
__device__ float g_gates[TOTAL_NODES];

// ---------------------------------------------------------------------------
// Kernel 1: pure streaming gate computation. No barriers, no smem.
// grid = 1024 CTAs x 256 thr = 8192 warps, 32 nodes/warp, exact cover.
// ---------------------------------------------------------------------------
__global__ __launch_bounds__(256, 8)
void gate_kernel(const float* __restrict__ feat,
                 const float* __restrict__ w)
{
    const int lane = threadIdx.x & 31;
    const int warp = threadIdx.x >> 5;
    const int gwarp = blockIdx.x * 8 + warp;
    const int base  = gwarp * 32;            // first node of this warp's chunk

    // weight slice held in registers (8 floats/lane, same every node)
    const float4 w0 = *reinterpret_cast<const float4*>(w + lane * 8);
    const float4 w1 = *reinterpret_cast<const float4*>(w + lane * 8 + 4);

    float keep = 0.0f;  // gate of node (base + lane), collected via lane match

    #pragma unroll
    for (int j4 = 0; j4 < 32; j4 += 4) {
        const float* r0 = feat + (size_t)(base + j4 + 0) * DIM + lane * 8;
        const float* r1 = feat + (size_t)(base + j4 + 1) * DIM + lane * 8;
        const float* r2 = feat + (size_t)(base + j4 + 2) * DIM + lane * 8;
        const float* r3 = feat + (size_t)(base + j4 + 3) * DIM + lane * 8;
        // front-batched loads: 8 independent LDG.128 in flight
        float4 a0 = *reinterpret_cast<const float4*>(r0);
        float4 b0 = *reinterpret_cast<const float4*>(r0 + 4);
        float4 a1 = *reinterpret_cast<const float4*>(r1);
        float4 b1 = *reinterpret_cast<const float4*>(r1 + 4);
        float4 a2 = *reinterpret_cast<const float4*>(r2);
        float4 b2 = *reinterpret_cast<const float4*>(r2 + 4);
        float4 a3 = *reinterpret_cast<const float4*>(r3);
        float4 b3 = *reinterpret_cast<const float4*>(r3 + 4);

        float p0 = a0.x*w0.x + a0.y*w0.y + a0.z*w0.z + a0.w*w0.w
                 + b0.x*w1.x + b0.y*w1.y + b0.z*w1.z + b0.w*w1.w;
        float p1 = a1.x*w0.x + a1.y*w0.y + a1.z*w0.z + a1.w*w0.w
                 + b1.x*w1.x + b1.y*w1.y + b1.z*w1.z + b1.w*w1.w;
        float p2 = a2.x*w0.x + a2.y*w0.y + a2.z*w0.z + a2.w*w0.w
                 + b2.x*w1.x + b2.y*w1.y + b2.z*w1.z + b2.w*w1.w;
        float p3 = a3.x*w0.x + a3.y*w0.y + a3.z*w0.z + a3.w*w0.w
                 + b3.x*w1.x + b3.y*w1.y + b3.z*w1.z + b3.w*w1.w;

        #pragma unroll
        for (int o = 16; o; o >>= 1) {
            p0 += __shfl_xor_sync(0xffffffffu, p0, o);
            p1 += __shfl_xor_sync(0xffffffffu, p1, o);
            p2 += __shfl_xor_sync(0xffffffffu, p2, o);
            p3 += __shfl_xor_sync(0xffffffffu, p3, o);
        }
        // after xor-butterfly every lane holds the full sum; keep own node's
        if (lane == j4 + 0) keep = p0;
        if (lane == j4 + 1) keep = p1;
        if (lane == j4 + 2) keep = p2;
        if (lane == j4 + 3) keep = p3;
    }
    // coalesced 128B store per warp (bias omitted: constant shift, order-invariant)
    g_gates[base + lane] = keep;
}

// order-preserving float -> uint encoding (ascending)
__device__ __forceinline__ unsigned ordf(float f) {
    unsigned b = __float_as_uint(f);
    return (b & 0x80000000u) ? ~b : (b | 0x80000000u);
}

// ---------------------------------------------------------------------------
// Kernel 2: per-graph top-32 (warp 0, REDUX-accelerated) + row gather (4 warps)
// ---------------------------------------------------------------------------
__global__ __launch_bounds__(128, 8)
void topk_gather_kernel(const float* __restrict__ feat,
                        float* __restrict__ out)
{
    __shared__ int topk_s[TOPK];

    const int lane = threadIdx.x & 31;
    const int warp = threadIdx.x >> 5;
    const int g    = blockIdx.x;
    const float* fbase = feat + (size_t)g * NP * DIM;

    if (warp == 0) {
        // 512 gates -> 16 order-encoded uints per lane, coalesced loads
        unsigned u[16];
        #pragma unroll
        for (int j = 0; j < 16; j++)
            u[j] = ordf(g_gates[g * NP + lane + 32 * j]);

        for (int k = 0; k < TOPK; k++) {
            // lane-local argmax, first occurrence wins (smallest j)
            unsigned best = u[0]; int bj = 0;
            #pragma unroll
            for (int j = 1; j < 16; j++)
                if (u[j] > best) { best = u[j]; bj = j; }
            // warp max via REDUX, then min-index tie-break via REDUX
            unsigned umax = __reduce_max_sync(0xffffffffu, best);
            int cand = (best == umax) ? (lane + (bj << 5)) : 0x7fffffff;
            int bi = __reduce_min_sync(0xffffffffu, cand);
            if (lane == 0) topk_s[k] = bi;
            if ((bi & 31) == lane) u[bi >> 5] = 0u;   // retire (0 < any finite enc)
        }
    }
    __syncthreads();

    // gather: 4 warps x 8 rows, 1KB per row, fully coalesced
    #pragma unroll
    for (int k = warp; k < TOPK; k += 4) {
        const int nid = topk_s[k];
        const float* src = fbase + (size_t)nid * DIM + lane * 8;
        float*       dst = out + ((size_t)g * TOPK + k) * DIM + lane * 8;
        float4 a0 = *reinterpret_cast<const float4*>(src);
        float4 a1 = *reinterpret_cast<const float4*>(src + 4);
        *reinterpret_cast<float4*>(dst)     = a0;
        *reinterpret_cast<float4*>(dst + 4) = a1;
    }
}

extern "C" void kernel_launch(void* const* d_in, const int* in_sizes, int n_in,
                              void* d_out, int out_size)
{
    const float* feat = (const float*)d_in[0];
    const float* w    = (const float*)d_in[1];
    // d_in[2] = bias (constant shift, no effect on top-k order)
    // d_in[3] = segment_ids (fixed 512-per-graph layout, implicit)
    float* out = (float*)d_out;

    gate_kernel<<<1024, 256>>>(feat, w);
    topk_gather_kernel<<<BGRAPHS, 128>>>(feat, out);
}

// round 6
// speedup vs baseline: 1.0707x; 1.0707x over previous
#include <cuda_runtime.h>
#include <math.h>

#define BGRAPHS 512
#define NP      512
#define DIM     256
#define TOPK    32

// allocation-free scratch
__device__ float g_gates[BGRAPHS * NP];
__device__ int   g_cnt[BGRAPHS];          // zero-init; reset in-kernel each run

// order-preserving float -> uint encoding (ascending)
__device__ __forceinline__ unsigned ordf(float f) {
    unsigned b = __float_as_uint(f);
    return (b & 0x80000000u) ? ~b : (b | 0x80000000u);
}

// 1024 CTAs x 256 threads: CTA (2g+h) streams gates for half-graph (g,h).
// Second CTA of each pair to finish does top-32 + gather for the whole graph,
// overlapping with other CTAs' streaming. First finisher exits immediately.
__global__ __launch_bounds__(256, 4)
void fused_pool_kernel(const float* __restrict__ feat,
                       const float* __restrict__ w,
                       float* __restrict__ out)
{
    __shared__ int s_ticket;
    __shared__ int topk_s[TOPK];

    const int tid  = threadIdx.x;
    const int lane = tid & 31;
    const int warp = tid >> 5;
    const int g    = blockIdx.x >> 1;
    const int half = blockIdx.x & 1;
    const int base = g * NP + half * 256 + warp * 32;   // 32 nodes per warp

    // weight slice in registers (8 floats/lane)
    const float4 w0 = *reinterpret_cast<const float4*>(w + lane * 8);
    const float4 w1 = *reinterpret_cast<const float4*>(w + lane * 8 + 4);

    // -------- Phase A: gates for 32 contiguous nodes (4-batched, MLP=8) ----
    float keep = 0.0f;
    #pragma unroll
    for (int j4 = 0; j4 < 32; j4 += 4) {
        const float* r0 = feat + (size_t)(base + j4 + 0) * DIM + lane * 8;
        const float* r1 = feat + (size_t)(base + j4 + 1) * DIM + lane * 8;
        const float* r2 = feat + (size_t)(base + j4 + 2) * DIM + lane * 8;
        const float* r3 = feat + (size_t)(base + j4 + 3) * DIM + lane * 8;
        float4 a0 = *reinterpret_cast<const float4*>(r0);
        float4 b0 = *reinterpret_cast<const float4*>(r0 + 4);
        float4 a1 = *reinterpret_cast<const float4*>(r1);
        float4 b1 = *reinterpret_cast<const float4*>(r1 + 4);
        float4 a2 = *reinterpret_cast<const float4*>(r2);
        float4 b2 = *reinterpret_cast<const float4*>(r2 + 4);
        float4 a3 = *reinterpret_cast<const float4*>(r3);
        float4 b3 = *reinterpret_cast<const float4*>(r3 + 4);

        float p0 = a0.x*w0.x + a0.y*w0.y + a0.z*w0.z + a0.w*w0.w
                 + b0.x*w1.x + b0.y*w1.y + b0.z*w1.z + b0.w*w1.w;
        float p1 = a1.x*w0.x + a1.y*w0.y + a1.z*w0.z + a1.w*w0.w
                 + b1.x*w1.x + b1.y*w1.y + b1.z*w1.z + b1.w*w1.w;
        float p2 = a2.x*w0.x + a2.y*w0.y + a2.z*w0.z + a2.w*w0.w
                 + b2.x*w1.x + b2.y*w1.y + b2.z*w1.z + b2.w*w1.w;
        float p3 = a3.x*w0.x + a3.y*w0.y + a3.z*w0.z + a3.w*w0.w
                 + b3.x*w1.x + b3.y*w1.y + b3.z*w1.z + b3.w*w1.w;

        #pragma unroll
        for (int o = 16; o; o >>= 1) {
            p0 += __shfl_xor_sync(0xffffffffu, p0, o);
            p1 += __shfl_xor_sync(0xffffffffu, p1, o);
            p2 += __shfl_xor_sync(0xffffffffu, p2, o);
            p3 += __shfl_xor_sync(0xffffffffu, p3, o);
        }
        if (lane == j4 + 0) keep = p0;
        if (lane == j4 + 1) keep = p1;
        if (lane == j4 + 2) keep = p2;
        if (lane == j4 + 3) keep = p3;
    }
    g_gates[base + lane] = keep;   // coalesced 128B per warp

    // -------- pairing handshake: second arriver owns the tail work --------
    __syncthreads();
    if (tid == 0) {
        __threadfence();                       // release our gate stores
        s_ticket = atomicAdd(&g_cnt[g], 1);
    }
    __syncthreads();
    if (s_ticket == 0) return;                 // first finisher: free the SM slot

    __threadfence();                           // acquire peer CTA's gate stores
    if (tid == 0) g_cnt[g] = 0;                // reset for next graph replay

    // -------- Phase B: warp 0 top-32 (desc, ties -> smaller idx) ----------
    if (warp == 0) {
        unsigned u[16];
        #pragma unroll
        for (int j = 0; j < 16; j++)
            u[j] = ordf(g_gates[g * NP + lane + 32 * j]);

        for (int k = 0; k < TOPK; k++) {
            unsigned best = u[0]; int bj = 0;
            #pragma unroll
            for (int j = 1; j < 16; j++)
                if (u[j] > best) { best = u[j]; bj = j; }
            unsigned umax = __reduce_max_sync(0xffffffffu, best);
            int cand = (best == umax) ? (lane + (bj << 5)) : 0x7fffffff;
            int bi = __reduce_min_sync(0xffffffffu, cand);
            if (lane == 0) topk_s[k] = bi;
            if ((bi & 31) == lane) u[bi >> 5] = 0u;    // retire winner
        }
    }
    __syncthreads();

    // -------- Phase C: 8 warps gather 4 rows each (likely L2-warm) --------
    const float* fbase = feat + (size_t)g * NP * DIM;
    #pragma unroll
    for (int k = warp; k < TOPK; k += 8) {
        const int nid = topk_s[k];
        const float* src = fbase + (size_t)nid * DIM + lane * 8;
        float*       dst = out + ((size_t)g * TOPK + k) * DIM + lane * 8;
        float4 a0 = *reinterpret_cast<const float4*>(src);
        float4 a1 = *reinterpret_cast<const float4*>(src + 4);
        *reinterpret_cast<float4*>(dst)     = a0;
        *reinterpret_cast<float4*>(dst + 4) = a1;
    }
}

extern "C" void kernel_launch(void* const* d_in, const int* in_sizes, int n_in,
                              void* d_out, int out_size)
{
    const float* feat = (const float*)d_in[0];
    const float* w    = (const float*)d_in[1];
    // d_in[2] = bias (constant shift, order-invariant -> dead code)
    // d_in[3] = segment_ids (fixed 512-per-graph layout, implicit)
    float* out = (float*)d_out;

    fused_pool_kernel<<<BGRAPHS * 2, 256>>>(feat, w, out);
}